// round 7
// baseline (speedup 1.0000x reference)
#include <cuda_runtime.h>
#include <math_constants.h>

#define BATCH 512
#define IN_DIM 1024
#define OUT_DIM 1024
#define KC 16
#define XLD 132   // dup-x row stride (floats): 16B-aligned, gcd(132,32)=4 -> ~2-way STS.64
#define WLD 68    // w row stride
#define NCHUNK (IN_DIM / KC)

typedef unsigned long long u64;

__device__ __forceinline__ u64 pack2(float a, float b) {
    u64 r; asm("mov.b64 %0, {%1, %2};" : "=l"(r) : "f"(a), "f"(b)); return r;
}
__device__ __forceinline__ u64 ffma2(u64 a, u64 b, u64 c) {
    // packed lane-wise fma: (a.lo*b.lo+c.lo, a.hi*b.hi+c.hi) -> single FFMA2 in SASS
    u64 r; asm("fma.rn.f32x2 %0, %1, %2, %3;" : "=l"(r) : "l"(a), "l"(b), "l"(c)); return r;
}
__device__ __forceinline__ void unpack2(u64 v, float& lo, float& hi) {
    asm("mov.b64 {%0, %1}, %2;" : "=f"(lo), "=f"(hi) : "l"(v));
}

__global__ __launch_bounds__(256, 1)
void tropical_linear_kernel(const float* __restrict__ x,
                            const float* __restrict__ W,
                            float* __restrict__ y,
                            const float one) {
    __shared__ float xs[2][KC][XLD];   // duplicated: xs[.][k][2b] == xs[.][k][2b+1]
    __shared__ float ws[2][KC][WLD];

    const int t  = threadIdx.x;
    const int tx = t & 15;        // o-direction (0..15), 4 cols each
    const int ty = t >> 4;        // b-direction (0..15), 4 rows each
    const int o0 = blockIdx.x * 64;
    const int b0 = blockIdx.y * 64;

    const int lc = t & 15;        // k within chunk (coalesced)
    const int lr = t >> 4;        // row group (0..15), rows lr + 16j

    const u64 one2 = pack2(one, one);

    float acc[4][4];
#pragma unroll
    for (int i = 0; i < 4; i++)
#pragma unroll
        for (int j = 0; j < 4; j++)
            acc[i][j] = -CUDART_INF_F;

    const float* xp = x + (b0 + lr) * IN_DIM + lc;
    const float* wp = W + (o0 + lr) * IN_DIM + lc;

    // prologue: chunk 0 -> regs -> smem buf 0
    float xg[4], wg[4];
#pragma unroll
    for (int j = 0; j < 4; j++) {
        xg[j] = xp[j * 16 * IN_DIM];
        wg[j] = wp[j * 16 * IN_DIM];
    }
#pragma unroll
    for (int j = 0; j < 4; j++) {
        float2 d; d.x = xg[j]; d.y = xg[j];
        *(float2*)&xs[0][lc][2 * (lr + 16 * j)] = d;
        ws[0][lc][lr + 16 * j] = wg[j];
    }
    __syncthreads();

    for (int c = 0; c < NCHUNK; c++) {
        const int p = c & 1;

        // prefetch next chunk into registers (overlaps compute)
        if (c + 1 < NCHUNK) {
            const float* xp2 = xp + (c + 1) * KC;
            const float* wp2 = wp + (c + 1) * KC;
#pragma unroll
            for (int j = 0; j < 4; j++) {
                xg[j] = xp2[j * 16 * IN_DIM];
                wg[j] = wp2[j * 16 * IN_DIM];
            }
        }

        // compute: 8 FFMA2 (fma pipe) + 16 FMNMX (alu pipe) per kk
#pragma unroll
        for (int kk = 0; kk < KC; kk++) {
            float4 xd0 = *(const float4*)&xs[p][kk][ty * 8];      // (x0,x0,x1,x1)
            float4 xd1 = *(const float4*)&xs[p][kk][ty * 8 + 4];  // (x2,x2,x3,x3)
            float4 wf  = *(const float4*)&ws[p][kk][tx * 4];      // w0..w3

            u64 xsp[4];
            xsp[0] = pack2(xd0.x, xd0.y);   // natural aligned pairs -> free packs
            xsp[1] = pack2(xd0.z, xd0.w);
            xsp[2] = pack2(xd1.x, xd1.y);
            xsp[3] = pack2(xd1.z, xd1.w);
            u64 w01 = pack2(wf.x, wf.y);
            u64 w23 = pack2(wf.z, wf.w);

#pragma unroll
            for (int i = 0; i < 4; i++) {
                float s0, s1;
                unpack2(ffma2(w01, one2, xsp[i]), s0, s1);
                acc[i][0] = fmaxf(acc[i][0], s0);
                acc[i][1] = fmaxf(acc[i][1], s1);
                unpack2(ffma2(w23, one2, xsp[i]), s0, s1);
                acc[i][2] = fmaxf(acc[i][2], s0);
                acc[i][3] = fmaxf(acc[i][3], s1);
            }
        }

        // stage next chunk into the other buffer
        if (c + 1 < NCHUNK) {
#pragma unroll
            for (int j = 0; j < 4; j++) {
                float2 d; d.x = xg[j]; d.y = xg[j];
                *(float2*)&xs[p ^ 1][lc][2 * (lr + 16 * j)] = d;
                ws[p ^ 1][lc][lr + 16 * j] = wg[j];
            }
        }
        __syncthreads();
    }

    // epilogue: vectorized stores
#pragma unroll
    for (int i = 0; i < 4; i++) {
        const int b = b0 + ty * 4 + i;
        float4 v = make_float4(acc[i][0], acc[i][1], acc[i][2], acc[i][3]);
        *(float4*)&y[b * OUT_DIM + o0 + tx * 4] = v;
    }
}

extern "C" void kernel_launch(void* const* d_in, const int* in_sizes, int n_in,
                              void* d_out, int out_size) {
    const float* x = (const float*)d_in[0];   // [512, 1024]
    const float* W = (const float*)d_in[1];   // [1024, 1024]
    float* y = (float*)d_out;                  // [512, 1024]

    dim3 grid(OUT_DIM / 64, BATCH / 64);  // 128 CTAs, 1 wave
    dim3 block(256);
    tropical_linear_kernel<<<grid, block>>>(x, W, y, 1.0f);
}